// round 1
// baseline (speedup 1.0000x reference)
#include <cuda_runtime.h>
#include <cuda_bf16.h>

#define N_SPOTS 50000
#define N_NEIGH 32
#define N_PROG  128

// Global scratch accumulator (no device allocation allowed).
__device__ double g_accum;

__global__ void zero_accum_kernel() {
    g_accum = 0.0;
}

// One warp per spot row i. Lane l holds float4 = p_i[4l..4l+3].
// Loop over 32 neighbors; each neighbor row load is a fully coalesced
// 512B (32 lanes x float4) read that should hit L2 (p fits in L2).
__global__ __launch_bounds__(256) void consistency_kernel(
    const float* __restrict__ probs,
    const float* __restrict__ weights,
    const int*   __restrict__ nidx)
{
    const int lane     = threadIdx.x & 31;
    const int warpInBl = threadIdx.x >> 5;
    const int warpsPerBlock = blockDim.x >> 5;
    const int gwarp   = blockIdx.x * warpsPerBlock + warpInBl;
    const int nWarps  = gridDim.x * warpsPerBlock;

    double warp_local = 0.0;

    for (int i = gwarp; i < N_SPOTS; i += nWarps) {
        // p_i: 128 floats, lane l owns floats [4l, 4l+4)
        const float4 pi =
            reinterpret_cast<const float4*>(probs + (size_t)i * N_PROG)[lane];

        // Each lane loads one neighbor index + weight; broadcast via shuffle.
        const int   myj = nidx[(size_t)i * N_NEIGH + lane];
        const float myw = weights[(size_t)i * N_NEIGH + lane];

        float rowsum = 0.f;

        #pragma unroll 8
        for (int k = 0; k < N_NEIGH; ++k) {
            const int   j  = __shfl_sync(0xffffffffu, myj, k);
            const float wk = __shfl_sync(0xffffffffu, myw, k);

            const float4 pj = __ldg(
                reinterpret_cast<const float4*>(probs + (size_t)j * N_PROG) + lane);

            const float dx = pi.x - pj.x;
            const float dy = pi.y - pj.y;
            const float dz = pi.z - pj.z;
            const float dw = pi.w - pj.w;
            float s = dx * dx + dy * dy + dz * dz + dw * dw;

            // Warp reduction across the 128 feature dims (32 lanes).
            s += __shfl_xor_sync(0xffffffffu, s, 16);
            s += __shfl_xor_sync(0xffffffffu, s, 8);
            s += __shfl_xor_sync(0xffffffffu, s, 4);
            s += __shfl_xor_sync(0xffffffffu, s, 2);
            s += __shfl_xor_sync(0xffffffffu, s, 1);

            rowsum = fmaf(wk, s, rowsum);
        }
        warp_local += (double)rowsum;
    }

    // Block reduction of per-warp doubles, one global atomic per block.
    __shared__ double sh[8];  // up to 8 warps per 256-thread block
    if (lane == 0) sh[warpInBl] = warp_local;
    __syncthreads();
    if (threadIdx.x == 0) {
        double blk = 0.0;
        for (int w = 0; w < warpsPerBlock; ++w) blk += sh[w];
        atomicAdd(&g_accum, blk);
    }
}

__global__ void finalize_kernel(float* __restrict__ out) {
    out[0] = (float)(g_accum / (double)N_SPOTS);
}

extern "C" void kernel_launch(void* const* d_in, const int* in_sizes, int n_in,
                              void* d_out, int out_size) {
    const float* probs   = (const float*)d_in[0];
    const float* weights = (const float*)d_in[1];
    const int*   nidx    = (const int*)d_in[2];
    float* out = (float*)d_out;

    zero_accum_kernel<<<1, 1>>>();

    // 256 threads = 8 warps per block; 2048 blocks = 16384 warps,
    // ~3 rows per warp (grid-stride) for MLP + load balance.
    consistency_kernel<<<2048, 256>>>(probs, weights, nidx);

    finalize_kernel<<<1, 1>>>(out);
}

// round 2
// speedup vs baseline: 1.3547x; 1.3547x over previous
#include <cuda_runtime.h>
#include <cuda_fp16.h>
#include <cuda_bf16.h>

#define N_SPOTS 50000
#define N_NEIGH 32
#define N_PROG  128

// Global scratch (device globals are the allowed scratch mechanism).
__device__ double g_accum;
__device__ __half g_probs_h[(size_t)N_SPOTS * N_PROG];  // 12.8 MB fp16 copy

__global__ void zero_accum_kernel() {
    g_accum = 0.0;
}

// Convert fp32 probs -> fp16 scratch. 6.4M elems, 4 per thread.
__global__ __launch_bounds__(256) void convert_kernel(
    const float* __restrict__ probs)
{
    const size_t total4 = (size_t)N_SPOTS * N_PROG / 4;
    size_t idx = (size_t)blockIdx.x * blockDim.x + threadIdx.x;
    const size_t stride = (size_t)gridDim.x * blockDim.x;
    const float4* __restrict__ src = reinterpret_cast<const float4*>(probs);
    __half2* __restrict__ dst = reinterpret_cast<__half2*>(g_probs_h);
    for (; idx < total4; idx += stride) {
        float4 v = src[idx];
        dst[2 * idx + 0] = __floats2half2_rn(v.x, v.y);
        dst[2 * idx + 1] = __floats2half2_rn(v.z, v.w);
    }
}

// One warp per spot row i. Lane l owns dims [4l, 4l+4) as 2x half2.
// Each lane accumulates its weighted per-dim partial across all 32
// neighbors (sum order swap: sum_k w_k sum_d == sum_d sum_k w_k), so the
// 5-shuffle cross-lane reduction happens ONCE per row, not per neighbor.
__global__ __launch_bounds__(256) void consistency_kernel(
    const float* __restrict__ weights,
    const int*   __restrict__ nidx)
{
    const int lane     = threadIdx.x & 31;
    const int warpInBl = threadIdx.x >> 5;
    const int warpsPerBlock = blockDim.x >> 5;
    const int gwarp   = blockIdx.x * warpsPerBlock + warpInBl;
    const int nWarps  = gridDim.x * warpsPerBlock;

    const __half2* __restrict__ ph2 =
        reinterpret_cast<const __half2*>(g_probs_h);

    double warp_local = 0.0;

    for (int i = gwarp; i < N_SPOTS; i += nWarps) {
        // Own row: lane loads 4 halves (8 bytes, coalesced 256B/warp).
        const size_t rowBase = (size_t)i * (N_PROG / 2) + lane * 2;
        const __half2 pi0 = ph2[rowBase + 0];
        const __half2 pi1 = ph2[rowBase + 1];

        // Lane l pre-loads neighbor l's index/weight; broadcast via shuffle.
        const int   myj = nidx[(size_t)i * N_NEIGH + lane];
        const float myw = weights[(size_t)i * N_NEIGH + lane];

        float acc = 0.f;

        #pragma unroll 8
        for (int k = 0; k < N_NEIGH; ++k) {
            const int   j  = __shfl_sync(0xffffffffu, myj, k);
            const float wk = __shfl_sync(0xffffffffu, myw, k);

            const size_t nb = (size_t)j * (N_PROG / 2) + lane * 2;
            const __half2 pj0 = ph2[nb + 0];
            const __half2 pj1 = ph2[nb + 1];

            // Diff in half2 (error negligible vs dx magnitude), square in fp32.
            const float2 d0 = __half22float2(__hsub2(pi0, pj0));
            const float2 d1 = __half22float2(__hsub2(pi1, pj1));

            float s = d0.x * d0.x;
            s = fmaf(d0.y, d0.y, s);
            s = fmaf(d1.x, d1.x, s);
            s = fmaf(d1.y, d1.y, s);
            acc = fmaf(wk, s, acc);
        }

        // Single cross-lane reduction per row.
        acc += __shfl_xor_sync(0xffffffffu, acc, 16);
        acc += __shfl_xor_sync(0xffffffffu, acc, 8);
        acc += __shfl_xor_sync(0xffffffffu, acc, 4);
        acc += __shfl_xor_sync(0xffffffffu, acc, 2);
        acc += __shfl_xor_sync(0xffffffffu, acc, 1);

        warp_local += (double)acc;
    }

    __shared__ double sh[8];
    if (lane == 0) sh[warpInBl] = warp_local;
    __syncthreads();
    if (threadIdx.x == 0) {
        double blk = 0.0;
        for (int w = 0; w < warpsPerBlock; ++w) blk += sh[w];
        atomicAdd(&g_accum, blk);
    }
}

__global__ void finalize_kernel(float* __restrict__ out) {
    out[0] = (float)(g_accum / (double)N_SPOTS);
}

extern "C" void kernel_launch(void* const* d_in, const int* in_sizes, int n_in,
                              void* d_out, int out_size) {
    const float* probs   = (const float*)d_in[0];
    const float* weights = (const float*)d_in[1];
    const int*   nidx    = (const int*)d_in[2];
    float* out = (float*)d_out;

    zero_accum_kernel<<<1, 1>>>();
    convert_kernel<<<2048, 256>>>(probs);
    consistency_kernel<<<2048, 256>>>(weights, nidx);
    finalize_kernel<<<1, 1>>>(out);
}